// round 13
// baseline (speedup 1.0000x reference)
#include <cuda_runtime.h>
#include <cuda_bf16.h>
#include <cstdint>

#define D_OUT_ 32768
#define D_IN_  1024

// Scratch (device globals: allocation-free rule)
static __device__ __nv_bfloat16 g_dw[(size_t)D_OUT_ * D_IN_];   // 64 MB bf16(DeltaW)
static __device__ __nv_bfloat16 g_sig[(size_t)D_IN_ * D_IN_];   // 2 MB bf16(Sigma)
static __device__ float  g_g[D_OUT_];                            // per-row g accum
static __device__ double g_acc[3];  // 0: act, 1: binary reg, 2: sum g^2
// producer/consumer state (re-zeroed by init_kernel every launch)
static __device__ int g_scnt[256];   // per-strip completion counters (target 8)
static __device__ int g_sigdone;     // sigma task counter (target 8)
static __device__ int g_task;        // prep task queue head
static __device__ int g_unit;        // gemm unit queue head

// ---------------- PTX helpers (baseline PTX only; no sm_103a features) -----
__device__ __forceinline__ uint32_t smem_u32(const void* p) {
    uint32_t a;
    asm("{ .reg .u64 t; cvta.to.shared.u64 t, %1; cvt.u32.u64 %0, t; }" : "=r"(a) : "l"(p));
    return a;
}
#define CPA16(dst, src) \
    asm volatile("cp.async.cg.shared.global [%0], [%1], 16;" :: "r"(dst), "l"(src))
#define CPCOMMIT() asm volatile("cp.async.commit_group;" ::: "memory")
#define CPWAIT(n)  asm volatile("cp.async.wait_group %0;" :: "n"(n) : "memory")

#define LDSM4(r0, r1, r2, r3, a) \
    asm volatile("ldmatrix.sync.aligned.m8n8.x4.shared.b16 {%0,%1,%2,%3}, [%4];" \
        : "=r"(r0), "=r"(r1), "=r"(r2), "=r"(r3) : "r"(a))

#define MMA16816(c0, c1, c2, c3, a0, a1, a2, a3, b0, b1) \
    asm volatile("mma.sync.aligned.m16n8k16.row.col.f32.bf16.bf16.f32 " \
        "{%0,%1,%2,%3}, {%4,%5,%6,%7}, {%8,%9}, {%0,%1,%2,%3};" \
        : "+f"(c0), "+f"(c1), "+f"(c2), "+f"(c3) \
        : "r"(a0), "r"(a1), "r"(a2), "r"(a3), "r"(b0), "r"(b1))

#define SWZ(o) ((o) ^ (((o) >> 3) & 0x70))

__device__ __forceinline__ float2 bf2f2(uint32_t v) {
    __nv_bfloat162 b;
    *reinterpret_cast<uint32_t*>(&b) = v;
    return __bfloat1622float2(b);
}
__device__ __forceinline__ float tanha(float x) {
    float y;
    asm("tanh.approx.f32 %0, %1;" : "=f"(y) : "f"(x));
    return y;
}

// ---------------- kernels --------------------------------------------------

__global__ void init_kernel() {
    int i = blockIdx.x * blockDim.x + threadIdx.x;
    if (i < D_OUT_) g_g[i] = 0.f;
    if (i < 3) g_acc[i] = 0.0;
    if (i < 256) g_scnt[i] = 0;
    if (i == 0) { g_sigdone = 0; g_task = 0; g_unit = 0; }
}

// Fused persistent kernel: 296 CTAs.
//  - CTAs 200..295: drain prep task queue first (8 sigma-eighth tasks +
//    2048 strip-eighth DW tasks), flagging per-strip readiness.
//  - ALL CTAs: pull gemm units (128x128 tiles, ascending order = ascending
//    strip order) from a global counter; R8 streaming mainloop + epilogue.
#define NCTAS 296
#define NPREP_START 200
#define NTASKS (8 + 2048)
#define NUNITS 2048
#define STAGE_BYTES 32768             // 16 KB A + 16 KB B per stage
#define SMEM_BYTES  98304             // 3 stages

__global__ void __launch_bounds__(256, 2) fused_kernel(
    const float* __restrict__ Wf, const float* __restrict__ Sgf,
    const float* __restrict__ Qf, const float* __restrict__ sf,
    const float* __restrict__ Tf) {
    extern __shared__ char smem[];
    __shared__ int sh_bcast;
    __shared__ float red[8];
    const uint32_t s0 = smem_u32(smem);

    const int tid = threadIdx.x;
    const int lane = tid & 31, w = tid >> 5;

    // ================= producer phase (prep CTAs only) =================
    if (blockIdx.x >= NPREP_START) {
        const float4* W4 = (const float4*)Wf;
        const float4* Q4 = (const float4*)Qf;
        const float4* T4 = (const float4*)Tf;
        const float4* S4 = (const float4*)Sgf;
        while (true) {
            if (tid == 0) sh_bcast = atomicAdd(&g_task, 1);
            __syncthreads();
            const int t = sh_bcast;
            if (t >= NTASKS) break;
            if (t < 8) {
                // sigma eighth: 32768 float4
                uint2* out = (uint2*)g_sig;
                const int base = t * 32768;
                for (int i = base + tid; i < base + 32768; i += 256) {
                    float4 v = S4[i];
                    __nv_bfloat162 p0, p1;
                    p0.x = __float2bfloat16_rn(v.x); p0.y = __float2bfloat16_rn(v.y);
                    p1.x = __float2bfloat16_rn(v.z); p1.y = __float2bfloat16_rn(v.w);
                    uint2 u;
                    u.x = *reinterpret_cast<uint32_t*>(&p0);
                    u.y = *reinterpret_cast<uint32_t*>(&p1);
                    out[i] = u;
                }
                __threadfence();
                __syncthreads();
                if (tid == 0) atomicAdd(&g_sigdone, 1);
            } else {
                // DW strip-eighth: 16 rows = 4096 float4
                const int task = t - 8;
                const int st = task >> 3;
                const int base = ((st << 7) + ((task & 7) << 4)) << 8;
                uint2* out = (uint2*)g_dw;
                float br = 0.f;
                for (int i = base + tid; i < base + 4096; i += 256) {
                    const float sv = sf[i >> 8];
                    const float4 wv = W4[i], qv = Q4[i], tv = T4[i];
                    float th0 = __saturatef(fmaf(tanha(tv.x), 0.6f, 0.5f));
                    float th1 = __saturatef(fmaf(tanha(tv.y), 0.6f, 0.5f));
                    float th2 = __saturatef(fmaf(tanha(tv.z), 0.6f, 0.5f));
                    float th3 = __saturatef(fmaf(tanha(tv.w), 0.6f, 0.5f));
                    float d0 = wv.x - sv * (qv.x + th0);
                    float d1 = wv.y - sv * (qv.y + th1);
                    float d2 = wv.z - sv * (qv.z + th2);
                    float d3 = wv.w - sv * (qv.w + th3);
                    float x0 = 2.f * th0 - 1.f, x1 = 2.f * th1 - 1.f;
                    float x2 = 2.f * th2 - 1.f, x3 = 2.f * th3 - 1.f;
                    br += (1.f - x0 * x0) + (1.f - x1 * x1) + (1.f - x2 * x2) + (1.f - x3 * x3);
                    __nv_bfloat162 p0, p1;
                    p0.x = __float2bfloat16_rn(d0); p0.y = __float2bfloat16_rn(d1);
                    p1.x = __float2bfloat16_rn(d2); p1.y = __float2bfloat16_rn(d3);
                    uint2 u;
                    u.x = *reinterpret_cast<uint32_t*>(&p0);
                    u.y = *reinterpret_cast<uint32_t*>(&p1);
                    out[i] = u;
                }
                __threadfence();   // each thread: DW stores visible before flag
                #pragma unroll
                for (int o = 16; o; o >>= 1) br += __shfl_down_sync(0xFFFFFFFFu, br, o);
                if (lane == 0) red[w] = br;
                __syncthreads();
                if (tid == 0) {
                    float tt = 0.f;
                    #pragma unroll
                    for (int j = 0; j < 8; j++) tt += red[j];
                    atomicAdd(&g_acc[1], (double)tt);
                    atomicAdd(&g_scnt[st], 1);   // release flag
                }
            }
        }
    }

    // ================= consumer phase (all CTAs) =================
    const int wm = w & 3, wn = w >> 2;          // 4 warps along M, 2 along N
    const int grp = lane >> 2, qd = lane & 3;
    const int ldc = tid & 7;
    const int lr0 = tid >> 3;
    const uint32_t swo[4] = {
        (uint32_t)SWZ((lr0 +  0) * 128 + ldc * 16), (uint32_t)SWZ((lr0 + 32) * 128 + ldc * 16),
        (uint32_t)SWZ((lr0 + 64) * 128 + ldc * 16), (uint32_t)SWZ((lr0 + 96) * 128 + ldc * 16) };
    const int arow = wm * 32 + (lane & 7) + ((lane >> 3) & 1) * 8;
    const int akh  = (lane >> 4) & 1;
    const int asx  = (arow & 7);
    const int bnrow = wn * 64 + (lane & 7) + ((lane >> 4) & 1) * 8;
    const int bkh  = (lane >> 3) & 1;

    float act = 0.f;

    auto load_chunk = [&](int u, int kc, int stg) {
        const __nv_bfloat16* sa = g_dw  + (size_t)((u >> 3) << 7) * D_IN_ + kc * 64;
        const __nv_bfloat16* sb = g_sig + (size_t)((u & 7)  << 7) * D_IN_ + kc * 64;
        const uint32_t dA = s0 + stg * STAGE_BYTES;
        const uint32_t dB = dA + 16384;
        #pragma unroll
        for (int i = 0; i < 4; i++) {
            const int r = lr0 + i * 32;
            CPA16(dA + swo[i], sa + r * D_IN_ + ldc * 8);
            CPA16(dB + swo[i], sb + r * D_IN_ + ldc * 8);
        }
        CPCOMMIT();
    };

    // grab next unit; wait for its strip (and sigma) readiness
    auto grab_unit = [&]() -> int {
        if (tid == 0) {
            int u = atomicAdd(&g_unit, 1);
            if (u < NUNITS) {
                while (atomicAdd(&g_sigdone, 0) < 8) __nanosleep(1024);
                const int st = u >> 3;
                while (atomicAdd(&g_scnt[st], 0) < 8) __nanosleep(1024);
                __threadfence();   // acquire
            }
            sh_bcast = u;
        }
        __syncthreads();
        return sh_bcast;
    };

    int u_cur = grab_unit();
    int ch = 0;
    if (u_cur < NUNITS) {
        load_chunk(u_cur, 0, 0);
        load_chunk(u_cur, 1, 1);
    }

    while (u_cur < NUNITS) {
        const int u_next = grab_unit();
        const int m0 = (u_cur >> 3) << 7;
        const int n0 = (u_cur & 7)  << 7;

        float acc[2][8][4];
        #pragma unroll
        for (int mt = 0; mt < 2; mt++)
            #pragma unroll
            for (int nt = 0; nt < 8; nt++)
                #pragma unroll
                for (int jj = 0; jj < 4; jj++) acc[mt][nt][jj] = 0.f;

        #pragma unroll 1
        for (int kc = 0; kc < 16; kc++, ch++) {
            CPWAIT(1);
            __syncthreads();

            if (kc < 14)               load_chunk(u_cur, kc + 2, (ch + 2) % 3);
            else if (u_next < NUNITS)  load_chunk(u_next, kc - 14, (ch + 2) % 3);
            else                       CPCOMMIT();

            const uint32_t bA = s0 + (ch % 3) * STAGE_BYTES;
            const uint32_t bB = bA + 16384;

            #pragma unroll
            for (int ks = 0; ks < 4; ks++) {
                uint32_t a[2][4], b[8][2];
                #pragma unroll
                for (int mt = 0; mt < 2; mt++) {
                    uint32_t addr = bA + (arow + mt * 16) * 128 +
                                    (((ks * 2 + akh) ^ asx) * 16);
                    LDSM4(a[mt][0], a[mt][1], a[mt][2], a[mt][3], addr);
                }
                #pragma unroll
                for (int np = 0; np < 4; np++) {
                    const int n = bnrow + np * 16;
                    uint32_t addr = bB + n * 128 + (((ks * 2 + bkh) ^ (n & 7)) * 16);
                    LDSM4(b[2 * np][0], b[2 * np][1], b[2 * np + 1][0], b[2 * np + 1][1], addr);
                }
                #pragma unroll
                for (int mt = 0; mt < 2; mt++)
                    #pragma unroll
                    for (int nt = 0; nt < 8; nt++)
                        MMA16816(acc[mt][nt][0], acc[mt][nt][1], acc[mt][nt][2], acc[mt][nt][3],
                                 a[mt][0], a[mt][1], a[mt][2], a[mt][3],
                                 b[nt][0], b[nt][1]);
            }
        }

        // ---- fused warp-independent epilogue (R8/R12) ----
        #pragma unroll
        for (int mt = 0; mt < 2; mt++) {
            #pragma unroll
            for (int half = 0; half < 2; half++) {
                const int row = m0 + wm * 32 + mt * 16 + grp + half * 8;
                const float*         wrow = Wf   + (size_t)row * D_IN_ + n0 + wn * 64;
                const __nv_bfloat16* drow = g_dw + (size_t)row * D_IN_ + n0 + wn * 64;
                float ga = 0.f;
                #pragma unroll
                for (int nt = 0; nt < 8; nt++) {
                    const int col = nt * 8 + qd * 2;
                    float z0 = acc[mt][nt][half * 2 + 0];
                    float z1 = acc[mt][nt][half * 2 + 1];
                    float2 dv = bf2f2(*(const uint32_t*)(drow + col));
                    float2 wv = *(const float2*)(wrow + col);
                    act = fmaf(z0, dv.x, act); act = fmaf(z1, dv.y, act);
                    ga  = fmaf(z0, wv.x, ga);  ga  = fmaf(z1, wv.y, ga);
                }
                ga += __shfl_xor_sync(0xFFFFFFFFu, ga, 1);
                ga += __shfl_xor_sync(0xFFFFFFFFu, ga, 2);
                if (qd == 0) atomicAdd(&g_g[row], ga);
            }
        }
        u_cur = u_next;
    }

    // CTA reduce act -> double atomic
    #pragma unroll
    for (int o = 16; o; o >>= 1) act += __shfl_down_sync(0xFFFFFFFFu, act, o);
    __syncthreads();
    if (lane == 0) red[w] = act;
    __syncthreads();
    if (tid == 0) {
        float t = 0.f;
        #pragma unroll
        for (int jj = 0; jj < 8; jj++) t += red[jj];
        atomicAdd(&g_acc[0], (double)t);
    }
}

// parallel sum of g^2 into g_acc[2]
__global__ void sq_kernel() {
    const int tid = blockIdx.x * blockDim.x + threadIdx.x;
    double sg = 0.0;
    for (int i = tid; i < D_OUT_; i += gridDim.x * blockDim.x) {
        double v = (double)g_g[i];
        sg += v * v;
    }
    #pragma unroll
    for (int o = 16; o; o >>= 1) sg += __shfl_down_sync(0xFFFFFFFFu, sg, o);
    __shared__ double red[8];
    if ((threadIdx.x & 31) == 0) red[threadIdx.x >> 5] = sg;
    __syncthreads();
    if (threadIdx.x == 0) {
        double t = 0.0;
        #pragma unroll
        for (int j = 0; j < (int)(blockDim.x >> 5); j++) t += red[j];
        atomicAdd(&g_acc[2], t);
    }
}

__global__ void out_kernel(float* __restrict__ out) {
    // total = act + lamb_reg*br + lamb * 4 * sum(g^2)
    out[0] = (float)(g_acc[0] + 0.0002 * g_acc[1] + 0.2 * g_acc[2]);
}

// ---------------- launch ---------------------------------------------------
extern "C" void kernel_launch(void* const* d_in, const int* in_sizes, int n_in,
                              void* d_out, int out_size) {
    (void)in_sizes; (void)n_in; (void)out_size;
    const float* W  = (const float*)d_in[0];
    const float* Sg = (const float*)d_in[1];
    const float* Q  = (const float*)d_in[2];
    const float* s  = (const float*)d_in[3];
    const float* T  = (const float*)d_in[4];

    static bool attr_set = false;
    if (!attr_set) {
        cudaFuncSetAttribute(fused_kernel, cudaFuncAttributeMaxDynamicSharedMemorySize, SMEM_BYTES);
        attr_set = true;
    }

    init_kernel<<<64, 512>>>();
    fused_kernel<<<NCTAS, 256, SMEM_BYTES>>>(W, Sg, Q, s, T);
    sq_kernel<<<64, 256>>>();
    out_kernel<<<1, 1>>>((float*)d_out);
}

// round 14
// speedup vs baseline: 1.3873x; 1.3873x over previous
#include <cuda_runtime.h>
#include <cuda_bf16.h>
#include <cstdint>

#define D_OUT_ 32768
#define D_IN_  1024

// Scratch (device globals: allocation-free rule)
static __device__ __nv_bfloat16 g_dw[(size_t)D_OUT_ * D_IN_];   // 64 MB bf16(DeltaW)
static __device__ __nv_bfloat16 g_sig[(size_t)D_IN_ * D_IN_];   // 2 MB bf16(Sigma)
static __device__ float  g_g[D_OUT_];                            // per-row g accum
static __device__ double g_acc[3];  // 0: act, 1: binary reg, 2: sum g^2

// ---------------- PTX helpers (baseline PTX only; no sm_103a features) -----
__device__ __forceinline__ uint32_t smem_u32(const void* p) {
    uint32_t a;
    asm("{ .reg .u64 t; cvta.to.shared.u64 t, %1; cvt.u32.u64 %0, t; }" : "=r"(a) : "l"(p));
    return a;
}
#define CPA16(dst, src) \
    asm volatile("cp.async.cg.shared.global [%0], [%1], 16;" :: "r"(dst), "l"(src))
#define CPCOMMIT() asm volatile("cp.async.commit_group;" ::: "memory")
#define CPWAIT(n)  asm volatile("cp.async.wait_group %0;" :: "n"(n) : "memory")

#define LDSM4(r0, r1, r2, r3, a) \
    asm volatile("ldmatrix.sync.aligned.m8n8.x4.shared.b16 {%0,%1,%2,%3}, [%4];" \
        : "=r"(r0), "=r"(r1), "=r"(r2), "=r"(r3) : "r"(a))

#define MMA16816(c0, c1, c2, c3, a0, a1, a2, a3, b0, b1) \
    asm volatile("mma.sync.aligned.m16n8k16.row.col.f32.bf16.bf16.f32 " \
        "{%0,%1,%2,%3}, {%4,%5,%6,%7}, {%8,%9}, {%0,%1,%2,%3};" \
        : "+f"(c0), "+f"(c1), "+f"(c2), "+f"(c3) \
        : "r"(a0), "r"(a1), "r"(a2), "r"(a3), "r"(b0), "r"(b1))

#define SWZ(o) ((o) ^ (((o) >> 3) & 0x70))

__device__ __forceinline__ float2 bf2f2(uint32_t v) {
    __nv_bfloat162 b;
    *reinterpret_cast<uint32_t*>(&b) = v;
    return __bfloat1622float2(b);
}
__device__ __forceinline__ float tanha(float x) {
    float y;
    asm("tanh.approx.f32 %0, %1;" : "=f"(y) : "f"(x));
    return y;
}

// ---------------- kernels --------------------------------------------------

__global__ void init_kernel() {
    int i = blockIdx.x * blockDim.x + threadIdx.x;
    if (i < D_OUT_) g_g[i] = 0.f;
    if (i < 3) g_acc[i] = 0.0;
}

// Sigma->bf16 (prologue) + Th/DW (main, 2-way interleaved) + binary-reg sum.
__global__ void prep_kernel(const float4* __restrict__ W, const float4* __restrict__ Q,
                            const float* __restrict__ s, const float4* __restrict__ T,
                            const float4* __restrict__ S) {
    const int gtid = blockIdx.x * blockDim.x + threadIdx.x;
    const int gstr = gridDim.x * blockDim.x;

    // Sigma convert: 1024*1024/4 = 262144 float4
    {
        uint2* outs = reinterpret_cast<uint2*>(g_sig);
        for (int i = gtid; i < D_IN_ * D_IN_ / 4; i += gstr) {
            float4 v = S[i];
            __nv_bfloat162 p0, p1;
            p0.x = __float2bfloat16_rn(v.x); p0.y = __float2bfloat16_rn(v.y);
            p1.x = __float2bfloat16_rn(v.z); p1.y = __float2bfloat16_rn(v.w);
            uint2 u;
            u.x = *reinterpret_cast<uint32_t*>(&p0);
            u.y = *reinterpret_cast<uint32_t*>(&p1);
            outs[i] = u;
        }
    }

    const int n4 = D_OUT_ * D_IN_ / 4;
    const int half = n4 >> 1;
    float br = 0.f;
    uint2* out = reinterpret_cast<uint2*>(g_dw);

    for (int i = gtid; i < half; i += gstr) {
        const int i2 = i + half;
        const float sva = s[i >> 8];
        const float svb = s[i2 >> 8];
        const float4 wa = W[i],  qa = Q[i],  ta = T[i];
        const float4 wb = W[i2], qb = Q[i2], tb = T[i2];

        float tha0 = __saturatef(fmaf(tanha(ta.x), 0.6f, 0.5f));
        float tha1 = __saturatef(fmaf(tanha(ta.y), 0.6f, 0.5f));
        float tha2 = __saturatef(fmaf(tanha(ta.z), 0.6f, 0.5f));
        float tha3 = __saturatef(fmaf(tanha(ta.w), 0.6f, 0.5f));
        float thb0 = __saturatef(fmaf(tanha(tb.x), 0.6f, 0.5f));
        float thb1 = __saturatef(fmaf(tanha(tb.y), 0.6f, 0.5f));
        float thb2 = __saturatef(fmaf(tanha(tb.z), 0.6f, 0.5f));
        float thb3 = __saturatef(fmaf(tanha(tb.w), 0.6f, 0.5f));

        float da0 = wa.x - sva * (qa.x + tha0);
        float da1 = wa.y - sva * (qa.y + tha1);
        float da2 = wa.z - sva * (qa.z + tha2);
        float da3 = wa.w - sva * (qa.w + tha3);
        float db0 = wb.x - svb * (qb.x + thb0);
        float db1 = wb.y - svb * (qb.y + thb1);
        float db2 = wb.z - svb * (qb.z + thb2);
        float db3 = wb.w - svb * (qb.w + thb3);

        float xa0 = 2.f * tha0 - 1.f, xa1 = 2.f * tha1 - 1.f;
        float xa2 = 2.f * tha2 - 1.f, xa3 = 2.f * tha3 - 1.f;
        float xb0 = 2.f * thb0 - 1.f, xb1 = 2.f * thb1 - 1.f;
        float xb2 = 2.f * thb2 - 1.f, xb3 = 2.f * thb3 - 1.f;
        br += (1.f - xa0 * xa0) + (1.f - xa1 * xa1) + (1.f - xa2 * xa2) + (1.f - xa3 * xa3);
        br += (1.f - xb0 * xb0) + (1.f - xb1 * xb1) + (1.f - xb2 * xb2) + (1.f - xb3 * xb3);

        __nv_bfloat162 p0, p1;
        uint2 u;
        p0.x = __float2bfloat16_rn(da0); p0.y = __float2bfloat16_rn(da1);
        p1.x = __float2bfloat16_rn(da2); p1.y = __float2bfloat16_rn(da3);
        u.x = *reinterpret_cast<uint32_t*>(&p0);
        u.y = *reinterpret_cast<uint32_t*>(&p1);
        out[i] = u;
        p0.x = __float2bfloat16_rn(db0); p0.y = __float2bfloat16_rn(db1);
        p1.x = __float2bfloat16_rn(db2); p1.y = __float2bfloat16_rn(db3);
        u.x = *reinterpret_cast<uint32_t*>(&p0);
        u.y = *reinterpret_cast<uint32_t*>(&p1);
        out[i2] = u;
    }
    #pragma unroll
    for (int o = 16; o; o >>= 1) br += __shfl_down_sync(0xFFFFFFFFu, br, o);
    __shared__ float red[8];
    if ((threadIdx.x & 31) == 0) red[threadIdx.x >> 5] = br;
    __syncthreads();
    if (threadIdx.x == 0) {
        float t = 0.f;
        #pragma unroll
        for (int j = 0; j < 8; j++) t += red[j];
        atomicAdd(&g_acc[1], (double)t);
    }
}

// Persistent streaming GEMM: Z = DW @ Sigma^T.  (R8/R12 structure — validated)
// 2048 units = 256 M-tiles x 8 N-chunks (unit 128x128, full K). 296 CTAs, 2/SM.
// K-chunks stream through a 3-stage cp.async rotation ACROSS unit boundaries.
// 8 warps as 4(M) x 2(N), warp tile 32x64. Fused warp-independent epilogue.
#define NCTAS 296
#define STAGE_BYTES 32768             // 16 KB A + 16 KB B per stage
#define SMEM_BYTES  98304             // 3 stages

__global__ void __launch_bounds__(256, 2) gemm_kernel(const float* __restrict__ Wf) {
    extern __shared__ char smem[];
    const uint32_t s0 = smem_u32(smem);

    const int tid = threadIdx.x;
    const int lane = tid & 31, w = tid >> 5;
    const int wm = w & 3, wn = w >> 2;          // 4 warps along M, 2 along N
    const int grp = lane >> 2, qd = lane & 3;

    // --- work assignment: CTAs 0..271 get 7 units, 272..295 get 6 ---
    const int c = blockIdx.x;
    const int ucount = (c < 272) ? 7 : 6;
    const int ustart = (c < 272) ? 7 * c : 1904 + 6 * (c - 272);
    const int nch = ucount * 16;

    // cp.async coords (A and B tiles both 128 rows x 8 cols of 16B)
    const int ldc = tid & 7;
    const int lr0 = tid >> 3;
    const uint32_t swo[4] = {
        (uint32_t)SWZ((lr0 +  0) * 128 + ldc * 16), (uint32_t)SWZ((lr0 + 32) * 128 + ldc * 16),
        (uint32_t)SWZ((lr0 + 64) * 128 + ldc * 16), (uint32_t)SWZ((lr0 + 96) * 128 + ldc * 16) };

    // ldmatrix bases
    const int arow = wm * 32 + (lane & 7) + ((lane >> 3) & 1) * 8;  // + mt*16
    const int akh  = (lane >> 4) & 1;
    const int asx  = (arow & 7);
    const int bnrow = wn * 64 + (lane & 7) + ((lane >> 4) & 1) * 8; // + nt*16
    const int bkh  = (lane >> 3) & 1;

    float act = 0.f;

    auto load_chunk = [&](int ci) {
        const int u  = ustart + (ci >> 4);
        const int kc = ci & 15;
        const __nv_bfloat16* sa = g_dw  + (size_t)((u >> 3) << 7) * D_IN_ + kc * 64;
        const __nv_bfloat16* sb = g_sig + (size_t)((u & 7)  << 7) * D_IN_ + kc * 64;
        const uint32_t dA = s0 + (ci % 3) * STAGE_BYTES;
        const uint32_t dB = dA + 16384;
        #pragma unroll
        for (int i = 0; i < 4; i++) {
            const int r = lr0 + i * 32;
            CPA16(dA + swo[i], sa + r * D_IN_ + ldc * 8);
            CPA16(dB + swo[i], sb + r * D_IN_ + ldc * 8);
        }
        CPCOMMIT();
    };

    load_chunk(0);
    load_chunk(1);

    int ch = 0;
    #pragma unroll 1
    for (int j = 0; j < ucount; j++) {
        const int u  = ustart + j;
        const int m0 = (u >> 3) << 7;
        const int n0 = (u & 7)  << 7;

        float acc[2][8][4];
        #pragma unroll
        for (int mt = 0; mt < 2; mt++)
            #pragma unroll
            for (int nt = 0; nt < 8; nt++)
                #pragma unroll
                for (int jj = 0; jj < 4; jj++) acc[mt][nt][jj] = 0.f;

        #pragma unroll 1
        for (int kc = 0; kc < 16; kc++, ch++) {
            CPWAIT(1);
            __syncthreads();

            if (ch + 2 < nch) load_chunk(ch + 2);
            else              CPCOMMIT();

            const uint32_t bA = s0 + (ch % 3) * STAGE_BYTES;
            const uint32_t bB = bA + 16384;

            #pragma unroll
            for (int ks = 0; ks < 4; ks++) {
                uint32_t a[2][4], b[8][2];
                #pragma unroll
                for (int mt = 0; mt < 2; mt++) {
                    uint32_t addr = bA + (arow + mt * 16) * 128 +
                                    (((ks * 2 + akh) ^ asx) * 16);
                    LDSM4(a[mt][0], a[mt][1], a[mt][2], a[mt][3], addr);
                }
                #pragma unroll
                for (int np = 0; np < 4; np++) {
                    const int n = bnrow + np * 16;
                    uint32_t addr = bB + n * 128 + (((ks * 2 + bkh) ^ (n & 7)) * 16);
                    LDSM4(b[2 * np][0], b[2 * np][1], b[2 * np + 1][0], b[2 * np + 1][1], addr);
                }
                #pragma unroll
                for (int mt = 0; mt < 2; mt++)
                    #pragma unroll
                    for (int nt = 0; nt < 8; nt++)
                        MMA16816(acc[mt][nt][0], acc[mt][nt][1], acc[mt][nt][2], acc[mt][nt][3],
                                 a[mt][0], a[mt][1], a[mt][2], a[mt][3],
                                 b[nt][0], b[nt][1]);
            }
        }

        // ---- fused warp-independent epilogue ----
        #pragma unroll
        for (int mt = 0; mt < 2; mt++) {
            #pragma unroll
            for (int half = 0; half < 2; half++) {
                const int row = m0 + wm * 32 + mt * 16 + grp + half * 8;
                const float*         wrow = Wf   + (size_t)row * D_IN_ + n0 + wn * 64;
                const __nv_bfloat16* drow = g_dw + (size_t)row * D_IN_ + n0 + wn * 64;
                float ga = 0.f;
                #pragma unroll
                for (int nt = 0; nt < 8; nt++) {
                    const int col = nt * 8 + qd * 2;
                    float z0 = acc[mt][nt][half * 2 + 0];
                    float z1 = acc[mt][nt][half * 2 + 1];
                    float2 dv = bf2f2(*(const uint32_t*)(drow + col));
                    float2 wv = *(const float2*)(wrow + col);
                    act = fmaf(z0, dv.x, act); act = fmaf(z1, dv.y, act);
                    ga  = fmaf(z0, wv.x, ga);  ga  = fmaf(z1, wv.y, ga);
                }
                ga += __shfl_xor_sync(0xFFFFFFFFu, ga, 1);
                ga += __shfl_xor_sync(0xFFFFFFFFu, ga, 2);
                if (qd == 0) atomicAdd(&g_g[row], ga);
            }
        }
        // next unit's first CPWAIT + __syncthreads orders stage reuse
    }

    // CTA reduce act -> double atomic
    #pragma unroll
    for (int o = 16; o; o >>= 1) act += __shfl_down_sync(0xFFFFFFFFu, act, o);
    __shared__ float reda[8];
    if (lane == 0) reda[w] = act;
    __syncthreads();
    if (tid == 0) {
        float t = 0.f;
        #pragma unroll
        for (int jj = 0; jj < 8; jj++) t += reda[jj];
        atomicAdd(&g_acc[0], (double)t);
    }
}

// parallel sum of g^2 into g_acc[2]
__global__ void sq_kernel() {
    const int tid = blockIdx.x * blockDim.x + threadIdx.x;
    double sg = 0.0;
    for (int i = tid; i < D_OUT_; i += gridDim.x * blockDim.x) {
        double v = (double)g_g[i];
        sg += v * v;
    }
    #pragma unroll
    for (int o = 16; o; o >>= 1) sg += __shfl_down_sync(0xFFFFFFFFu, sg, o);
    __shared__ double red[8];
    if ((threadIdx.x & 31) == 0) red[threadIdx.x >> 5] = sg;
    __syncthreads();
    if (threadIdx.x == 0) {
        double t = 0.0;
        #pragma unroll
        for (int j = 0; j < (int)(blockDim.x >> 5); j++) t += red[j];
        atomicAdd(&g_acc[2], t);
    }
}

__global__ void out_kernel(float* __restrict__ out) {
    // total = act + lamb_reg*br + lamb * 4 * sum(g^2)
    out[0] = (float)(g_acc[0] + 0.0002 * g_acc[1] + 0.2 * g_acc[2]);
}

// ---------------- launch ---------------------------------------------------
extern "C" void kernel_launch(void* const* d_in, const int* in_sizes, int n_in,
                              void* d_out, int out_size) {
    (void)in_sizes; (void)n_in; (void)out_size;
    const float* W  = (const float*)d_in[0];
    const float* Sg = (const float*)d_in[1];
    const float* Q  = (const float*)d_in[2];
    const float* s  = (const float*)d_in[3];
    const float* T  = (const float*)d_in[4];

    static bool attr_set = false;
    if (!attr_set) {
        cudaFuncSetAttribute(gemm_kernel, cudaFuncAttributeMaxDynamicSharedMemorySize, SMEM_BYTES);
        attr_set = true;
    }

    init_kernel<<<64, 512>>>();
    prep_kernel<<<1024, 256>>>((const float4*)W, (const float4*)Q, s, (const float4*)T,
                               (const float4*)Sg);
    gemm_kernel<<<NCTAS, 256, SMEM_BYTES>>>(W);
    sq_kernel<<<64, 256>>>();
    out_kernel<<<1, 1>>>((float*)d_out);
}